// round 16
// baseline (speedup 1.0000x reference)
#include <cuda_runtime.h>
#include <cuda_bf16.h>
#include <stdint.h>

#define BS   16
#define MM   128
#define NA   8400
#define NC   80
#define KTOP 13
#define CAP  1024
#define EPS7 1e-7f
#define EPS9 1e-9f
#define FULL 0xffffffffu
#define CNT1 (1 << 20)   // packed claim increment: cnt in high bits, sum(m) low

// scratch (static device globals -- allowed)
__device__ int    g_cs  [BS * NA];    // packed: (cnt<<20) | sum_of_m
__device__ float  g_alsum[BS * NA];
__device__ float  g_ovsum[BS * NA];
__device__ unsigned long long g_best[BS * NA];
__device__ float  g_pos_am[BS * MM];
__device__ float  g_pos_ov[BS * MM];
__device__ int    g_tgt[BS * NA];
__device__ float  g_al [BS * NA];
__device__ int    g_multilist[BS * NA];
__device__ int    g_touched[BS * NA];
__device__ int    g_nmulti;
__device__ int    g_ntouched;
__device__ float4 g_gtbox[BS * MM];   // gt box
__device__ float4 g_gtaux[BS * MM];   // {at1, mask, label(int bits), unused}

// ---------------------------------------------------------------------------
// CIoU (identical math to reference _ciou + clip>=0)
// ---------------------------------------------------------------------------
__device__ __forceinline__ float ciou_core(const float4 g, const float4 p,
                                           float at_g, float at_p)
{
    const float c4pi2 = 0.40528473456935108577f;  // 4/pi^2
    float w1 = g.z - g.x, h1 = g.w - g.y + EPS7;
    float w2 = p.z - p.x, h2 = p.w - p.y + EPS7;
    float iw = fminf(g.z, p.z) - fmaxf(g.x, p.x);
    float ih = fminf(g.w, p.w) - fmaxf(g.y, p.y);
    float inter = fmaxf(iw, 0.f) * fmaxf(ih, 0.f);
    float uni = w1 * h1 + w2 * h2 - inter + EPS7;
    float iou = inter / uni;
    float cw = fmaxf(g.z, p.z) - fminf(g.x, p.x);
    float ch = fmaxf(g.w, p.w) - fminf(g.y, p.y);
    float c2 = cw * cw + ch * ch + EPS7;
    float dx = p.x + p.z - g.x - g.z;
    float dy = p.y + p.w - g.y - g.w;
    float rho2 = (dx * dx + dy * dy) * 0.25f;
    float dat = at_p - at_g;
    float v = c4pi2 * dat * dat;
    float alpha = v / (v - iou + (1.f + EPS7));
    return fmaxf(iou - (rho2 / c2 + v * alpha), 0.f);
}
__device__ __forceinline__ float ciou_hg(const float4 g, const float4 p, float at_g)
{
    return ciou_core(g, p, at_g, atanf((p.z - p.x) / (p.w - p.y + EPS7)));
}
__device__ __forceinline__ float dmin_xy(const float4 g, float ax, float ay)
{
    return fminf(fminf(ax - g.x, ay - g.y), fminf(g.z - ax, g.w - ay));
}

// ---------------------------------------------------------------------------
// K0: zero scratch + build GT prep table
// ---------------------------------------------------------------------------
__global__ __launch_bounds__(256) void k0_zero(
    const int*   __restrict__ gt_labels,
    const float* __restrict__ gt_bboxes,
    const float* __restrict__ mask_gt)
{
    int i = blockIdx.x * blockDim.x + threadIdx.x;
    if (i < BS * NA) {
        g_cs[i] = 0;
        g_alsum[i] = 0.f; g_ovsum[i] = 0.f;
    }
    if (i < BS * MM) {
        g_pos_am[i] = 0.f; g_pos_ov[i] = 0.f;
        float4 g = reinterpret_cast<const float4*>(gt_bboxes)[i];
        g_gtbox[i] = g;
        float4 aux;
        aux.x = atanf((g.z - g.x) / (g.w - g.y + EPS7));
        aux.y = mask_gt[i];
        aux.z = __int_as_float(gt_labels[i]);
        aux.w = 0.f;
        g_gtaux[i] = aux;
    }
    if (i == 0) { g_nmulti = 0; g_ntouched = 0; }
}

// ---------------------------------------------------------------------------
// KD (side stream): default outputs for ALL anchors: label/box of gt[b][0],
// fg=0, tgt=0. Touched anchors get overwritten by k1f/k3b2.
// ---------------------------------------------------------------------------
__global__ __launch_bounds__(256) void kD(float* __restrict__ out)
{
    int idx = blockIdx.x * blockDim.x + threadIdx.x;
    if (idx >= BS * NA) return;
    int b = idx / NA;
    int grow = b * MM;
    int lbl = max(__float_as_int(g_gtaux[grow].z), 0);
    float4 bx = g_gtbox[grow];

    float* o_lab = out;
    float* o_box = out + (size_t)BS * NA;
    float* o_fg  = out + (size_t)BS * NA * (5 + NC);
    float* o_tg  = o_fg + (size_t)BS * NA;
    o_lab[idx] = (float)lbl;
    reinterpret_cast<float4*>(o_box)[idx] = bx;
    o_fg[idx] = 0.f;
    o_tg[idx] = 0.f;
}

// ---------------------------------------------------------------------------
// K1f: ONE BLOCK (256 thr) per GT row. Phase 1: analytic enumeration of
// in-gts cells, positive align keys into SMEM. Phase 2: per-warp top-13.
// Phase 3: warp 0 merges -> global top-13 (value desc, index asc), claims +
// touched/multi lists + OPTIMISTIC per-anchor outputs (first claimer), and
// zero-fill. Runs after kD (writes out).
// ---------------------------------------------------------------------------
__global__ __launch_bounds__(256) void k1f(
    const float* __restrict__ pd_scores,
    const float* __restrict__ pd_bboxes,
    float* __restrict__ out)
{
    __shared__ unsigned long long scand[CAP];
    __shared__ unsigned long long swtop[8 * KTOP];
    __shared__ int scount;

    int row = blockIdx.x;                  // b*MM + m
    float4 aux = g_gtaux[row];
    if (aux.y <= 0.f) return;              // block-uniform
    int b = row >> 7, m = row & 127;
    int tid = threadIdx.x;
    int wid = tid >> 5, lane = tid & 31;

    float4 g = g_gtbox[row];
    float at1 = aux.x;
    int lbl = __float_as_int(aux.z);
    const float*  psb = pd_scores + (size_t)b * NA * NC + lbl;
    const float4* pbb = reinterpret_cast<const float4*>(pd_bboxes) + (size_t)b * NA;

    if (tid == 0) scount = 0;
    if (tid < 8 * KTOP) swtop[tid] = 0ull;

    // rect ranges (3 scales)
    int ix0s[3], iy0s[3], ws[3];
    int tot = 0, t0 = 0, t1 = 0;
    #pragma unroll
    for (int ks = 0; ks < 3; ++ks) {
        const int   n = (ks == 0) ? 80 : (ks == 1) ? 40 : 20;
        const float s = (ks == 0) ? 8.f : (ks == 1) ? 16.f : 32.f;
        int ix0 = max(0,     (int)floorf(g.x / s - 0.5f));
        int ix1 = min(n - 1, (int)floorf(g.z / s - 0.5f) + 1);
        int iy0 = max(0,     (int)floorf(g.y / s - 0.5f));
        int iy1 = min(n - 1, (int)floorf(g.w / s - 0.5f) + 1);
        int w = max(ix1 - ix0 + 1, 0), h = max(iy1 - iy0 + 1, 0);
        ix0s[ks] = ix0; iy0s[ks] = iy0; ws[ks] = w;
        if (ks == 0) t0 = w * h;
        if (ks == 1) t1 = w * h;
        tot += w * h;
    }
    __syncthreads();

    // Phase 1: enumerate + compute align metric, push positives to SMEM
    for (int t = tid; t < tot; t += 256) {
        int ks, tc;
        if (t < t0)            { ks = 0; tc = t; }
        else if (t < t0 + t1)  { ks = 1; tc = t - t0; }
        else                   { ks = 2; tc = t - t0 - t1; }
        const int   n   = (ks == 0) ? 80 : (ks == 1) ? 40 : 20;
        const float s   = (ks == 0) ? 8.f : (ks == 1) ? 16.f : 32.f;
        const int   off = (ks == 0) ? 0 : (ks == 1) ? 6400 : 8000;
        int ix = ix0s[ks] + tc % ws[ks];
        int iy = iy0s[ks] + tc / ws[ks];
        float ax = (ix + 0.5f) * s, ay = (iy + 0.5f) * s;
        if (dmin_xy(g, ax, ay) <= EPS9) continue;
        int idx = off + iy * n + ix;
        float ov = ciou_hg(g, pbb[idx], at1);
        if (ov <= 0.f) continue;
        float sc = psb[(size_t)idx * NC];
        float o2 = ov * ov;
        float al = sc * (o2 * o2 * o2);
        if (al <= 0.f) continue;
        int slot = atomicAdd(&scount, 1);
        scand[slot] =
            ((unsigned long long)__float_as_uint(al) << 32) |
            (unsigned)(0x7fffffff - idx);
    }
    __syncthreads();
    int ncand = scount;

    // Phase 2: per-warp top-13 over its striped candidates (<=4 per lane)
    {
        unsigned long long buf[4];
        #pragma unroll
        for (int j = 0; j < 4; ++j) {
            int p = tid + j * 256;
            buf[j] = (p < ncand) ? scand[p] : 0ull;
        }
        unsigned long long lmax = buf[0];
        #pragma unroll
        for (int j = 1; j < 4; ++j) if (buf[j] > lmax) lmax = buf[j];

        #pragma unroll 1
        for (int it = 0; it < KTOP; ++it) {
            unsigned hi  = (unsigned)(lmax >> 32);
            unsigned mhi = __reduce_max_sync(FULL, hi);
            if (mhi == 0u) break;
            unsigned lo  = (hi == mhi) ? (unsigned)lmax : 0u;
            unsigned mlo = __reduce_max_sync(FULL, lo);
            unsigned long long k = ((unsigned long long)mhi << 32) | mlo;
            if (lane == 0) swtop[wid * KTOP + it] = k;
            if (lmax == k) {               // unique owner (keys unique per row)
                #pragma unroll
                for (int j = 0; j < 4; ++j) if (buf[j] == k) buf[j] = 0ull;
                lmax = buf[0];
                #pragma unroll
                for (int j = 1; j < 4; ++j) if (buf[j] > lmax) lmax = buf[j];
            }
        }
    }
    __syncthreads();

    // Phase 3: warp 0 merges the 8x13 warp-local keys -> global top-13
    if (wid != 0) return;

    unsigned long long buf[4];
    #pragma unroll
    for (int j = 0; j < 4; ++j) {
        int p = lane + j * 32;
        buf[j] = (p < 8 * KTOP) ? swtop[p] : 0ull;
    }
    unsigned long long lmax = buf[0];
    #pragma unroll
    for (int j = 1; j < 4; ++j) if (buf[j] > lmax) lmax = buf[j];

    int   mysel = -1;
    float myval = 0.f;
    int qsel = 0;
    #pragma unroll 1
    for (int it = 0; it < KTOP; ++it) {
        unsigned hi  = (unsigned)(lmax >> 32);
        unsigned mhi = __reduce_max_sync(FULL, hi);
        if (mhi == 0u) break;
        unsigned lo  = (hi == mhi) ? (unsigned)lmax : 0u;
        unsigned mlo = __reduce_max_sync(FULL, lo);
        unsigned long long k = ((unsigned long long)mhi << 32) | mlo;
        if (lane == qsel) {
            mysel = 0x7fffffff - (int)mlo;
            myval = __uint_as_float(mhi);
        }
        qsel++;
        if (lmax == k) {
            #pragma unroll
            for (int j = 0; j < 4; ++j) if (buf[j] == k) buf[j] = 0ull;
            lmax = buf[0];
            #pragma unroll
            for (int j = 1; j < 4; ++j) if (buf[j] > lmax) lmax = buf[j];
        }
    }

    float* o_lab = out;
    float* o_box = out + (size_t)BS * NA;
    float* o_fg  = out + (size_t)BS * NA * (5 + NC);
    float* o_tg  = o_fg + (size_t)BS * NA;
    int lblc = max(lbl, 0);

    // claims; first claim (0->1) -> touched list + optimistic outputs;
    // second claim (1->2) -> multi list.
    if (lane < qsel) {
        float4 p = pbb[mysel];
        float ov = ciou_hg(g, p, at1);
        int gidx = b * NA + mysel;
        int old = atomicAdd(&g_cs[gidx], CNT1 | m);
        atomicAdd(&g_alsum[gidx], myval);
        atomicAdd(&g_ovsum[gidx], ov);
        int oc = old >> 20;
        bool first  = oc == 0;
        bool second = oc == 1;
        unsigned amask = (1u << qsel) - 1u;
        unsigned fm = __ballot_sync(amask, first);
        if (fm) {
            int leader = __ffs(fm) - 1;
            int base = 0;
            if (lane == leader) base = atomicAdd(&g_ntouched, __popc(fm));
            base = __shfl_sync(amask, base, leader);
            if (first)
                g_touched[base + __popc(fm & ((1u << lane) - 1))] = gidx;
        }
        if (first) {                       // optimistic resolve (cnt==1 case)
            g_tgt[gidx] = m;
            g_al [gidx] = myval;
            o_lab[gidx] = (float)lblc;
            reinterpret_cast<float4*>(o_box)[gidx] = g;
            o_fg[gidx] = 1.f;
            o_tg[gidx] = (float)m;
        }
        unsigned sm = __ballot_sync(amask, second);
        if (sm) {
            int leader = __ffs(sm) - 1;
            int base = 0;
            if (lane == leader) base = atomicAdd(&g_nmulti, __popc(sm));
            base = __shfl_sync(amask, base, leader);
            if (second) {
                int p2 = base + __popc(sm & ((1u << lane) - 1));
                g_multilist[p2] = gidx;
                g_best[p2] = (unsigned long long)(MM - 1);   // v=0, m=0
            }
        }
    }

    // zero-fill (rare): smallest-index zero-valued anchors of the full row
    if (qsel < KTOP) {
        int sarr[KTOP];
        for (int t = 0; t < qsel; ++t)
            sarr[t] = __shfl_sync(FULL, mysel, t);
        if (lane == 0) {
            int need = KTOP - qsel;
            int j = 0;
            while (need > 0 && j < 8 * KTOP) {
                bool ispos = false;
                for (int t = 0; t < qsel; ++t) if (sarr[t] == j) { ispos = true; break; }
                if (!ispos) {
                    int ix = j % 80, iy = j / 80;   // j small -> scale-8 grid
                    float ax = (ix + 0.5f) * 8.f, ay = (iy + 0.5f) * 8.f;
                    if (dmin_xy(g, ax, ay) > EPS9) {
                        float ov = ciou_hg(g, pbb[j], at1);
                        int gidx = b * NA + j;
                        int old = atomicAdd(&g_cs[gidx], CNT1 | m);
                        atomicAdd(&g_ovsum[gidx], ov);
                        int oc = old >> 20;
                        if (oc == 0) {
                            int p = atomicAdd(&g_ntouched, 1);
                            g_touched[p] = gidx;
                            g_tgt[gidx] = m;
                            g_al [gidx] = 0.f;
                            o_lab[gidx] = (float)lblc;
                            reinterpret_cast<float4*>(o_box)[gidx] = g;
                            o_fg[gidx] = 1.f;
                            o_tg[gidx] = (float)m;
                        } else if (oc == 1) {
                            int p = atomicAdd(&g_nmulti, 1);
                            g_multilist[p] = gidx;
                            g_best[p] = (unsigned long long)(MM - 1);
                        }
                    }
                    need--;
                }
                j++;
            }
        }
    }
}

// ---------------------------------------------------------------------------
// K3s (stream 3, concurrent with k3b1/k3b2): cnt==1 touched anchors push
// their carried al/ov into the per-GT maxima. Nothing else.
// ---------------------------------------------------------------------------
__global__ __launch_bounds__(256) void k3s()
{
    int nt = g_ntouched;
    int stride = gridDim.x * blockDim.x;
    for (int i = blockIdx.x * blockDim.x + threadIdx.x; i < nt; i += stride) {
        int idx = g_touched[i];
        int cs = g_cs[idx];
        if ((cs >> 20) == 1) {
            int b = idx / NA;
            int row = b * MM + (cs & 0xfffff);
            float al  = g_alsum[idx];
            float ovm = g_ovsum[idx];
            atomicMax((unsigned int*)&g_pos_am[row], __float_as_uint(al));
            atomicMax((unsigned int*)&g_pos_ov[row], __float_as_uint(ovm));
        }
    }
}

// ---------------------------------------------------------------------------
// K3b1: one THREAD per (entry, m): masked CIoU; atomicMax packed key
// (val<<32 | (MM-1-m)) only when v>0.
// ---------------------------------------------------------------------------
__global__ __launch_bounds__(256) void k3b1(
    const float* __restrict__ pd_bboxes,
    const float* __restrict__ anc)
{
    int tot = g_nmulti * MM;
    int stride = gridDim.x * blockDim.x;
    for (int t = blockIdx.x * blockDim.x + threadIdx.x; t < tot; t += stride) {
        int e = t >> 7, m = t & 127;
        int idx = g_multilist[e];
        int b = idx / NA, a = idx - b * NA;
        int row = b * MM + m;
        float4 aux = g_gtaux[row];
        if (aux.y <= 0.f) continue;
        float2 an = reinterpret_cast<const float2*>(anc)[a];
        float4 gg = g_gtbox[row];
        if (dmin_xy(gg, an.x, an.y) <= EPS9) continue;
        float4 p = reinterpret_cast<const float4*>(pd_bboxes)[idx];
        float at2 = atanf((p.z - p.x) / (p.w - p.y + EPS7));
        float v = ciou_core(gg, p, aux.x, at2);
        if (v > 0.f) {
            unsigned long long key =
                ((unsigned long long)__float_as_uint(v) << 32) |
                (unsigned)(MM - 1 - m);
            atomicMax(&g_best[e], key);
        }
    }
}

// ---------------------------------------------------------------------------
// K3b2: one thread per entry: unpack winner, finish entry (overwrites the
// optimistic first-claim outputs).
// ---------------------------------------------------------------------------
__global__ __launch_bounds__(256) void k3b2(
    const float* __restrict__ pd_scores,
    float* __restrict__ out)
{
    int nm = g_nmulti;
    int stride = gridDim.x * blockDim.x;
    for (int e = blockIdx.x * blockDim.x + threadIdx.x; e < nm; e += stride) {
        int idx = g_multilist[e];
        int b = idx / NA, a = idx - b * NA;
        unsigned long long k = g_best[e];
        int tgt = MM - 1 - (int)(k & 0xffffffffu);
        float ovm = __uint_as_float((unsigned)(k >> 32));
        int row = b * MM + tgt;
        int lbl = __float_as_int(g_gtaux[row].z);
        float al = 0.f;
        if (ovm > 0.f) {
            float sc = pd_scores[((size_t)b * NA + a) * NC + lbl];
            float o2 = ovm * ovm;
            al = sc * (o2 * o2 * o2);
        }
        atomicMax((unsigned int*)&g_pos_am[row], __float_as_uint(al));
        atomicMax((unsigned int*)&g_pos_ov[row], __float_as_uint(ovm));
        g_tgt[idx] = tgt;
        g_al [idx] = al;

        float4 bx = g_gtbox[row];
        float* o_lab = out;
        float* o_box = out + (size_t)BS * NA;
        float* o_fg  = out + (size_t)BS * NA * (5 + NC);
        float* o_tg  = o_fg + (size_t)BS * NA;
        o_lab[idx] = (float)max(lbl, 0);
        reinterpret_cast<float4*>(o_box)[idx] = bx;
        o_fg[idx] = 1.f;
        o_tg[idx] = (float)tgt;
    }
}

// ---------------------------------------------------------------------------
// K4: sparse nrm scatter over the touched list (scores pre-zeroed)
// ---------------------------------------------------------------------------
__global__ __launch_bounds__(256) void k4_scatter(float* __restrict__ out)
{
    float* o_sc = out + (size_t)BS * NA * 5;
    int nt = g_ntouched;
    int stride = gridDim.x * blockDim.x;
    for (int i = blockIdx.x * blockDim.x + threadIdx.x; i < nt; i += stride) {
        int idx = g_touched[i];
        int b = idx / NA;
        int tgt = g_tgt[idx];
        int grow = b * MM + tgt;
        int lbl = max(__float_as_int(g_gtaux[grow].z), 0);
        float nrm = g_al[idx] * g_pos_ov[grow] / (g_pos_am[grow] + EPS9);
        o_sc[(size_t)idx * NC + lbl] = nrm;
    }
}

// ---------------------------------------------------------------------------
extern "C" void kernel_launch(void* const* d_in, const int* in_sizes, int n_in,
                              void* d_out, int out_size)
{
    const float* pd_scores = (const float*)d_in[0];
    const float* pd_bboxes = (const float*)d_in[1];
    const float* anc       = (const float*)d_in[2];
    const int*   gt_labels = (const int*)  d_in[3];
    const float* gt_bboxes = (const float*)d_in[4];
    const float* mask_gt   = (const float*)d_in[5];
    float* out = (float*)d_out;

    static cudaStream_t s2 = nullptr, s3 = nullptr;
    static cudaEvent_t evFork = nullptr, evKD = nullptr, evJoin = nullptr;
    static cudaEvent_t evK1f = nullptr, evK3s = nullptr;
    if (!s2) {
        cudaStreamCreateWithFlags(&s2, cudaStreamNonBlocking);
        cudaStreamCreateWithFlags(&s3, cudaStreamNonBlocking);
        cudaEventCreateWithFlags(&evFork, cudaEventDisableTiming);
        cudaEventCreateWithFlags(&evKD,   cudaEventDisableTiming);
        cudaEventCreateWithFlags(&evJoin, cudaEventDisableTiming);
        cudaEventCreateWithFlags(&evK1f,  cudaEventDisableTiming);
        cudaEventCreateWithFlags(&evK3s,  cudaEventDisableTiming);
    }

    float* o_sc = out + (size_t)BS * NA * 5;
    int n = BS * NA;

    // main: prep
    k0_zero<<<(n + 255) / 256, 256>>>(gt_labels, gt_bboxes, mask_gt);

    // side s2: defaults (cheap) then score memset
    cudaEventRecord(evFork, 0);
    cudaStreamWaitEvent(s2, evFork, 0);
    kD<<<(n + 255) / 256, 256, 0, s2>>>(out);
    cudaEventRecord(evKD, s2);
    cudaMemsetAsync(o_sc, 0, (size_t)BS * NA * NC * sizeof(float), s2);
    cudaEventRecord(evJoin, s2);

    // main: fused metrics + top-13 + optimistic outputs (after kD defaults)
    cudaStreamWaitEvent(0, evKD, 0);
    k1f<<<BS * MM, 256>>>(pd_scores, pd_bboxes, out);
    cudaEventRecord(evK1f, 0);

    // side s3: cnt==1 pos_am/pos_ov maxima, concurrent with k3b1/k3b2
    cudaStreamWaitEvent(s3, evK1f, 0);
    k3s<<<128, 256, 0, s3>>>();
    cudaEventRecord(evK3s, s3);

    // main: multi resolution
    k3b1<<<2048, 256>>>(pd_bboxes, anc);
    k3b2<<<64, 256>>>(pd_scores, out);

    // join + final scatter
    cudaStreamWaitEvent(0, evK3s, 0);
    cudaStreamWaitEvent(0, evJoin, 0);
    k4_scatter<<<64, 256>>>(out);
}

// round 17
// speedup vs baseline: 1.1353x; 1.1353x over previous
#include <cuda_runtime.h>
#include <cuda_bf16.h>
#include <stdint.h>

#define BS   16
#define MM   128
#define NA   8400
#define NC   80
#define KTOP 13
#define CAP  1024
#define EPS7 1e-7f
#define EPS9 1e-9f
#define FULL 0xffffffffu
#define CNT1 (1 << 20)   // packed claim increment: cnt in high bits, sum(m) low

// scratch (static device globals -- allowed)
__device__ int    g_cs  [BS * NA];    // packed: (cnt<<20) | sum_of_m
__device__ float  g_alsum[BS * NA];
__device__ float  g_ovsum[BS * NA];
__device__ unsigned long long g_best[BS * NA];
__device__ float  g_pos_am[BS * MM];
__device__ float  g_pos_ov[BS * MM];
__device__ int    g_tgt[BS * NA];
__device__ float  g_al [BS * NA];
__device__ int    g_fglist[BS * NA];
__device__ int    g_multilist[BS * NA];
__device__ int    g_touched[BS * NA];
__device__ float4 g_trec[BS * NA];    // {al, ov, m(int bits), gidx(int bits)}
__device__ int    g_nfg;
__device__ int    g_nmulti;
__device__ int    g_ntouched;
__device__ float4 g_gtbox[BS * MM];   // gt box
__device__ float4 g_gtaux[BS * MM];   // {at1, mask, label(int bits), unused}

// ---------------------------------------------------------------------------
// CIoU (identical math to reference _ciou + clip>=0)
// ---------------------------------------------------------------------------
__device__ __forceinline__ float ciou_core(const float4 g, const float4 p,
                                           float at_g, float at_p)
{
    const float c4pi2 = 0.40528473456935108577f;  // 4/pi^2
    float w1 = g.z - g.x, h1 = g.w - g.y + EPS7;
    float w2 = p.z - p.x, h2 = p.w - p.y + EPS7;
    float iw = fminf(g.z, p.z) - fmaxf(g.x, p.x);
    float ih = fminf(g.w, p.w) - fmaxf(g.y, p.y);
    float inter = fmaxf(iw, 0.f) * fmaxf(ih, 0.f);
    float uni = w1 * h1 + w2 * h2 - inter + EPS7;
    float iou = inter / uni;
    float cw = fmaxf(g.z, p.z) - fminf(g.x, p.x);
    float ch = fmaxf(g.w, p.w) - fminf(g.y, p.y);
    float c2 = cw * cw + ch * ch + EPS7;
    float dx = p.x + p.z - g.x - g.z;
    float dy = p.y + p.w - g.y - g.w;
    float rho2 = (dx * dx + dy * dy) * 0.25f;
    float dat = at_p - at_g;
    float v = c4pi2 * dat * dat;
    float alpha = v / (v - iou + (1.f + EPS7));
    return fmaxf(iou - (rho2 / c2 + v * alpha), 0.f);
}
__device__ __forceinline__ float ciou_hg(const float4 g, const float4 p, float at_g)
{
    return ciou_core(g, p, at_g, atanf((p.z - p.x) / (p.w - p.y + EPS7)));
}
__device__ __forceinline__ float dmin_xy(const float4 g, float ax, float ay)
{
    return fminf(fminf(ax - g.x, ay - g.y), fminf(g.z - ax, g.w - ay));
}

// ---------------------------------------------------------------------------
// K0: zero scratch + build GT prep table
// ---------------------------------------------------------------------------
__global__ __launch_bounds__(256) void k0_zero(
    const int*   __restrict__ gt_labels,
    const float* __restrict__ gt_bboxes,
    const float* __restrict__ mask_gt)
{
    int i = blockIdx.x * blockDim.x + threadIdx.x;
    if (i < BS * NA) {
        g_cs[i] = 0;
        g_alsum[i] = 0.f; g_ovsum[i] = 0.f;
    }
    if (i < BS * MM) {
        g_pos_am[i] = 0.f; g_pos_ov[i] = 0.f;
        float4 g = reinterpret_cast<const float4*>(gt_bboxes)[i];
        g_gtbox[i] = g;
        float4 aux;
        aux.x = atanf((g.z - g.x) / (g.w - g.y + EPS7));
        aux.y = mask_gt[i];
        aux.z = __int_as_float(gt_labels[i]);
        aux.w = 0.f;
        g_gtaux[i] = aux;
    }
    if (i == 0) { g_nfg = 0; g_nmulti = 0; g_ntouched = 0; }
}

// ---------------------------------------------------------------------------
// KD (side stream): default outputs for ALL anchors: label/box of gt[b][0],
// fg=0, tgt=0. Touched anchors get overwritten by k3s/k3b2.
// ---------------------------------------------------------------------------
__global__ __launch_bounds__(256) void kD(float* __restrict__ out)
{
    int idx = blockIdx.x * blockDim.x + threadIdx.x;
    if (idx >= BS * NA) return;
    int b = idx / NA;
    int grow = b * MM;
    int lbl = max(__float_as_int(g_gtaux[grow].z), 0);
    float4 bx = g_gtbox[grow];

    float* o_lab = out;
    float* o_box = out + (size_t)BS * NA;
    float* o_fg  = out + (size_t)BS * NA * (5 + NC);
    float* o_tg  = o_fg + (size_t)BS * NA;
    o_lab[idx] = (float)lbl;
    reinterpret_cast<float4*>(o_box)[idx] = bx;
    o_fg[idx] = 0.f;
    o_tg[idx] = 0.f;
}

// ---------------------------------------------------------------------------
// K1f: ONE BLOCK (256 thr) per GT row. Phase 1: analytic enumeration of
// in-gts cells, positive align keys into SMEM. Phase 2: per-warp top-13
// (exact key order). Phase 3: warp 0 merges 8x13 keys -> global top-13
// (value desc, index asc), claims + touched/multi lists (+ per-touched
// record for the fast k3s path) + zero-fill.
// ---------------------------------------------------------------------------
__global__ __launch_bounds__(256) void k1f(
    const float* __restrict__ pd_scores,
    const float* __restrict__ pd_bboxes)
{
    __shared__ unsigned long long scand[CAP];
    __shared__ unsigned long long swtop[8 * KTOP];
    __shared__ int scount;

    int row = blockIdx.x;                  // b*MM + m
    float4 aux = g_gtaux[row];
    if (aux.y <= 0.f) return;              // block-uniform
    int b = row >> 7, m = row & 127;
    int tid = threadIdx.x;
    int wid = tid >> 5, lane = tid & 31;

    float4 g = g_gtbox[row];
    float at1 = aux.x;
    int lbl = __float_as_int(aux.z);
    const float*  psb = pd_scores + (size_t)b * NA * NC + lbl;
    const float4* pbb = reinterpret_cast<const float4*>(pd_bboxes) + (size_t)b * NA;

    if (tid == 0) scount = 0;
    if (tid < 8 * KTOP) swtop[tid] = 0ull;

    // rect ranges (3 scales)
    int ix0s[3], iy0s[3], ws[3];
    int tot = 0, t0 = 0, t1 = 0;
    #pragma unroll
    for (int ks = 0; ks < 3; ++ks) {
        const int   n = (ks == 0) ? 80 : (ks == 1) ? 40 : 20;
        const float s = (ks == 0) ? 8.f : (ks == 1) ? 16.f : 32.f;
        int ix0 = max(0,     (int)floorf(g.x / s - 0.5f));
        int ix1 = min(n - 1, (int)floorf(g.z / s - 0.5f) + 1);
        int iy0 = max(0,     (int)floorf(g.y / s - 0.5f));
        int iy1 = min(n - 1, (int)floorf(g.w / s - 0.5f) + 1);
        int w = max(ix1 - ix0 + 1, 0), h = max(iy1 - iy0 + 1, 0);
        ix0s[ks] = ix0; iy0s[ks] = iy0; ws[ks] = w;
        if (ks == 0) t0 = w * h;
        if (ks == 1) t1 = w * h;
        tot += w * h;
    }
    __syncthreads();

    // Phase 1: enumerate + compute align metric, push positives to SMEM
    for (int t = tid; t < tot; t += 256) {
        int ks, tc;
        if (t < t0)            { ks = 0; tc = t; }
        else if (t < t0 + t1)  { ks = 1; tc = t - t0; }
        else                   { ks = 2; tc = t - t0 - t1; }
        const int   n   = (ks == 0) ? 80 : (ks == 1) ? 40 : 20;
        const float s   = (ks == 0) ? 8.f : (ks == 1) ? 16.f : 32.f;
        const int   off = (ks == 0) ? 0 : (ks == 1) ? 6400 : 8000;
        int ix = ix0s[ks] + tc % ws[ks];
        int iy = iy0s[ks] + tc / ws[ks];
        float ax = (ix + 0.5f) * s, ay = (iy + 0.5f) * s;
        if (dmin_xy(g, ax, ay) <= EPS9) continue;
        int idx = off + iy * n + ix;
        float ov = ciou_hg(g, pbb[idx], at1);
        if (ov <= 0.f) continue;
        float sc = psb[(size_t)idx * NC];
        float o2 = ov * ov;
        float al = sc * (o2 * o2 * o2);
        if (al <= 0.f) continue;
        int slot = atomicAdd(&scount, 1);
        scand[slot] =
            ((unsigned long long)__float_as_uint(al) << 32) |
            (unsigned)(0x7fffffff - idx);
    }
    __syncthreads();
    int ncand = scount;

    // Phase 2: per-warp top-13 over its striped candidates (<=4 per lane)
    {
        unsigned long long buf[4];
        #pragma unroll
        for (int j = 0; j < 4; ++j) {
            int p = tid + j * 256;
            buf[j] = (p < ncand) ? scand[p] : 0ull;
        }
        unsigned long long lmax = buf[0];
        #pragma unroll
        for (int j = 1; j < 4; ++j) if (buf[j] > lmax) lmax = buf[j];

        #pragma unroll 1
        for (int it = 0; it < KTOP; ++it) {
            unsigned hi  = (unsigned)(lmax >> 32);
            unsigned mhi = __reduce_max_sync(FULL, hi);
            if (mhi == 0u) break;
            unsigned lo  = (hi == mhi) ? (unsigned)lmax : 0u;
            unsigned mlo = __reduce_max_sync(FULL, lo);
            unsigned long long k = ((unsigned long long)mhi << 32) | mlo;
            if (lane == 0) swtop[wid * KTOP + it] = k;
            if (lmax == k) {               // unique owner (keys unique per row)
                #pragma unroll
                for (int j = 0; j < 4; ++j) if (buf[j] == k) buf[j] = 0ull;
                lmax = buf[0];
                #pragma unroll
                for (int j = 1; j < 4; ++j) if (buf[j] > lmax) lmax = buf[j];
            }
        }
    }
    __syncthreads();

    // Phase 3: warp 0 merges the 8x13 warp-local keys -> global top-13
    if (wid != 0) return;

    unsigned long long buf[4];
    #pragma unroll
    for (int j = 0; j < 4; ++j) {
        int p = lane + j * 32;
        buf[j] = (p < 8 * KTOP) ? swtop[p] : 0ull;
    }
    unsigned long long lmax = buf[0];
    #pragma unroll
    for (int j = 1; j < 4; ++j) if (buf[j] > lmax) lmax = buf[j];

    int   mysel = -1;
    float myval = 0.f;
    int qsel = 0;
    #pragma unroll 1
    for (int it = 0; it < KTOP; ++it) {
        unsigned hi  = (unsigned)(lmax >> 32);
        unsigned mhi = __reduce_max_sync(FULL, hi);
        if (mhi == 0u) break;
        unsigned lo  = (hi == mhi) ? (unsigned)lmax : 0u;
        unsigned mlo = __reduce_max_sync(FULL, lo);
        unsigned long long k = ((unsigned long long)mhi << 32) | mlo;
        if (lane == qsel) {
            mysel = 0x7fffffff - (int)mlo;
            myval = __uint_as_float(mhi);
        }
        qsel++;
        if (lmax == k) {
            #pragma unroll
            for (int j = 0; j < 4; ++j) if (buf[j] == k) buf[j] = 0ull;
            lmax = buf[0];
            #pragma unroll
            for (int j = 1; j < 4; ++j) if (buf[j] > lmax) lmax = buf[j];
        }
    }

    // claims; first claim (0->1) -> touched list + record; second (1->2) ->
    // multi list.
    if (lane < qsel) {
        float4 p = pbb[mysel];
        float ov = ciou_hg(g, p, at1);
        int gidx = b * NA + mysel;
        int old = atomicAdd(&g_cs[gidx], CNT1 | m);
        atomicAdd(&g_alsum[gidx], myval);
        atomicAdd(&g_ovsum[gidx], ov);
        int oc = old >> 20;
        bool first  = oc == 0;
        bool second = oc == 1;
        unsigned amask = (1u << qsel) - 1u;
        unsigned fm = __ballot_sync(amask, first);
        if (fm) {
            int leader = __ffs(fm) - 1;
            int base = 0;
            if (lane == leader) base = atomicAdd(&g_ntouched, __popc(fm));
            base = __shfl_sync(amask, base, leader);
            if (first) {
                int p1 = base + __popc(fm & ((1u << lane) - 1));
                g_touched[p1] = gidx;
                g_trec[p1] = make_float4(myval, ov,
                                         __int_as_float(m),
                                         __int_as_float(gidx));
            }
        }
        unsigned sm = __ballot_sync(amask, second);
        if (sm) {
            int leader = __ffs(sm) - 1;
            int base = 0;
            if (lane == leader) base = atomicAdd(&g_nmulti, __popc(sm));
            base = __shfl_sync(amask, base, leader);
            if (second) {
                int p2 = base + __popc(sm & ((1u << lane) - 1));
                g_multilist[p2] = gidx;
                g_best[p2] = (unsigned long long)(MM - 1);   // v=0, m=0
            }
        }
    }

    // zero-fill (rare): smallest-index zero-valued anchors of the full row
    if (qsel < KTOP) {
        int sarr[KTOP];
        for (int t = 0; t < qsel; ++t)
            sarr[t] = __shfl_sync(FULL, mysel, t);
        if (lane == 0) {
            int need = KTOP - qsel;
            int j = 0;
            while (need > 0 && j < 8 * KTOP) {
                bool ispos = false;
                for (int t = 0; t < qsel; ++t) if (sarr[t] == j) { ispos = true; break; }
                if (!ispos) {
                    int ix = j % 80, iy = j / 80;   // j small -> scale-8 grid
                    float ax = (ix + 0.5f) * 8.f, ay = (iy + 0.5f) * 8.f;
                    if (dmin_xy(g, ax, ay) > EPS9) {
                        float ov = ciou_hg(g, pbb[j], at1);
                        int gidx = b * NA + j;
                        int old = atomicAdd(&g_cs[gidx], CNT1 | m);
                        atomicAdd(&g_ovsum[gidx], ov);
                        int oc = old >> 20;
                        if (oc == 0) {
                            int p = atomicAdd(&g_ntouched, 1);
                            g_touched[p] = gidx;
                            g_trec[p] = make_float4(0.f, ov,
                                                    __int_as_float(m),
                                                    __int_as_float(gidx));
                        } else if (oc == 1) {
                            int p = atomicAdd(&g_nmulti, 1);
                            g_multilist[p] = gidx;
                            g_best[p] = (unsigned long long)(MM - 1);
                        }
                    }
                    need--;
                }
                j++;
            }
        }
    }
}

// ---------------------------------------------------------------------------
// K3s (stream 3, concurrent with k3b1/k3b2): resolve cnt==1 touched anchors
// from the coalesced record (short chain); cnt!=1 skipped (k3b2 handles).
// ---------------------------------------------------------------------------
__global__ __launch_bounds__(256) void k3s(float* __restrict__ out)
{
    int nt = g_ntouched;
    int stride = gridDim.x * blockDim.x;

    for (int i = blockIdx.x * blockDim.x + threadIdx.x; i < nt; i += stride) {
        float4 rec = g_trec[i];            // coalesced 16B
        int gidx = __float_as_int(rec.w);
        int m    = __float_as_int(rec.z);
        int b = gidx / NA;
        int row = b * MM + m;
        // row/label/box loads do not depend on the scattered cs load
        int lbl = max(__float_as_int(g_gtaux[row].z), 0);
        float4 bx = g_gtbox[row];
        int cs = g_cs[gidx];
        if ((cs >> 20) != 1) continue;     // multi: handled by k3b2

        atomicMax((unsigned int*)&g_pos_am[row], __float_as_uint(rec.x));
        atomicMax((unsigned int*)&g_pos_ov[row], __float_as_uint(rec.y));
        g_tgt[gidx] = m;
        g_al [gidx] = rec.x;

        float* o_lab = out;
        float* o_box = out + (size_t)BS * NA;
        float* o_fg  = out + (size_t)BS * NA * (5 + NC);
        float* o_tg  = o_fg + (size_t)BS * NA;
        o_lab[gidx] = (float)lbl;
        reinterpret_cast<float4*>(o_box)[gidx] = bx;
        o_fg[gidx] = 1.f;
        o_tg[gidx] = (float)m;
    }
}

// ---------------------------------------------------------------------------
// K3b1: one THREAD per (entry, m): masked CIoU; atomicMax packed key
// (val<<32 | (MM-1-m)) only when v>0.
// ---------------------------------------------------------------------------
__global__ __launch_bounds__(256) void k3b1(
    const float* __restrict__ pd_bboxes,
    const float* __restrict__ anc)
{
    int tot = g_nmulti * MM;
    int stride = gridDim.x * blockDim.x;
    for (int t = blockIdx.x * blockDim.x + threadIdx.x; t < tot; t += stride) {
        int e = t >> 7, m = t & 127;
        int idx = g_multilist[e];
        int b = idx / NA, a = idx - b * NA;
        int row = b * MM + m;
        float4 aux = g_gtaux[row];
        if (aux.y <= 0.f) continue;
        float2 an = reinterpret_cast<const float2*>(anc)[a];
        float4 gg = g_gtbox[row];
        if (dmin_xy(gg, an.x, an.y) <= EPS9) continue;
        float4 p = reinterpret_cast<const float4*>(pd_bboxes)[idx];
        float at2 = atanf((p.z - p.x) / (p.w - p.y + EPS7));
        float v = ciou_core(gg, p, aux.x, at2);
        if (v > 0.f) {
            unsigned long long key =
                ((unsigned long long)__float_as_uint(v) << 32) |
                (unsigned)(MM - 1 - m);
            atomicMax(&g_best[e], key);
        }
    }
}

// ---------------------------------------------------------------------------
// K3b2: one thread per entry: unpack winner, finish entry.
// ---------------------------------------------------------------------------
__global__ __launch_bounds__(256) void k3b2(
    const float* __restrict__ pd_scores,
    float* __restrict__ out)
{
    int nm = g_nmulti;
    int stride = gridDim.x * blockDim.x;
    for (int e = blockIdx.x * blockDim.x + threadIdx.x; e < nm; e += stride) {
        int idx = g_multilist[e];
        int b = idx / NA, a = idx - b * NA;
        unsigned long long k = g_best[e];
        int tgt = MM - 1 - (int)(k & 0xffffffffu);
        float ovm = __uint_as_float((unsigned)(k >> 32));
        int row = b * MM + tgt;
        int lbl = __float_as_int(g_gtaux[row].z);
        float al = 0.f;
        if (ovm > 0.f) {
            float sc = pd_scores[((size_t)b * NA + a) * NC + lbl];
            float o2 = ovm * ovm;
            al = sc * (o2 * o2 * o2);
        }
        atomicMax((unsigned int*)&g_pos_am[row], __float_as_uint(al));
        atomicMax((unsigned int*)&g_pos_ov[row], __float_as_uint(ovm));
        g_tgt[idx] = tgt;
        g_al [idx] = al;

        float4 bx = g_gtbox[row];
        float* o_lab = out;
        float* o_box = out + (size_t)BS * NA;
        float* o_fg  = out + (size_t)BS * NA * (5 + NC);
        float* o_tg  = o_fg + (size_t)BS * NA;
        o_lab[idx] = (float)max(lbl, 0);
        reinterpret_cast<float4*>(o_box)[idx] = bx;
        o_fg[idx] = 1.f;
        o_tg[idx] = (float)tgt;
    }
}

// ---------------------------------------------------------------------------
// K4: sparse nrm scatter over the touched list (scores pre-zeroed)
// ---------------------------------------------------------------------------
__global__ __launch_bounds__(256) void k4_scatter(float* __restrict__ out)
{
    float* o_sc = out + (size_t)BS * NA * 5;
    int nt = g_ntouched;
    int stride = gridDim.x * blockDim.x;
    for (int i = blockIdx.x * blockDim.x + threadIdx.x; i < nt; i += stride) {
        int idx = g_touched[i];
        int b = idx / NA;
        int tgt = g_tgt[idx];
        int grow = b * MM + tgt;
        int lbl = max(__float_as_int(g_gtaux[grow].z), 0);
        float nrm = g_al[idx] * g_pos_ov[grow] / (g_pos_am[grow] + EPS9);
        o_sc[(size_t)idx * NC + lbl] = nrm;
    }
}

// ---------------------------------------------------------------------------
extern "C" void kernel_launch(void* const* d_in, const int* in_sizes, int n_in,
                              void* d_out, int out_size)
{
    const float* pd_scores = (const float*)d_in[0];
    const float* pd_bboxes = (const float*)d_in[1];
    const float* anc       = (const float*)d_in[2];
    const int*   gt_labels = (const int*)  d_in[3];
    const float* gt_bboxes = (const float*)d_in[4];
    const float* mask_gt   = (const float*)d_in[5];
    float* out = (float*)d_out;

    static cudaStream_t s2 = nullptr, s3 = nullptr;
    static cudaEvent_t evFork = nullptr, evKD = nullptr, evJoin = nullptr;
    static cudaEvent_t evK1f = nullptr, evK3s = nullptr;
    if (!s2) {
        cudaStreamCreateWithFlags(&s2, cudaStreamNonBlocking);
        cudaStreamCreateWithFlags(&s3, cudaStreamNonBlocking);
        cudaEventCreateWithFlags(&evFork, cudaEventDisableTiming);
        cudaEventCreateWithFlags(&evKD,   cudaEventDisableTiming);
        cudaEventCreateWithFlags(&evJoin, cudaEventDisableTiming);
        cudaEventCreateWithFlags(&evK1f,  cudaEventDisableTiming);
        cudaEventCreateWithFlags(&evK3s,  cudaEventDisableTiming);
    }

    float* o_sc = out + (size_t)BS * NA * 5;
    int n = BS * NA;

    // main: prep
    k0_zero<<<(n + 255) / 256, 256>>>(gt_labels, gt_bboxes, mask_gt);

    // side s2: defaults (cheap) then score memset
    cudaEventRecord(evFork, 0);
    cudaStreamWaitEvent(s2, evFork, 0);
    kD<<<(n + 255) / 256, 256, 0, s2>>>(out);
    cudaEventRecord(evKD, s2);
    cudaMemsetAsync(o_sc, 0, (size_t)BS * NA * NC * sizeof(float), s2);
    cudaEventRecord(evJoin, s2);

    // main: fused metrics + top-13 (builds touched/multi lists + records)
    k1f<<<BS * MM, 256>>>(pd_scores, pd_bboxes);
    cudaEventRecord(evK1f, 0);

    // side s3: cnt==1 resolution, concurrent with k3b1/k3b2
    cudaStreamWaitEvent(s3, evK1f, 0);
    cudaStreamWaitEvent(s3, evKD, 0);
    k3s<<<128, 256, 0, s3>>>(out);
    cudaEventRecord(evK3s, s3);

    // main: multi resolution
    k3b1<<<2048, 256>>>(pd_bboxes, anc);
    cudaStreamWaitEvent(0, evKD, 0);       // k3b2 writes outputs over defaults
    k3b2<<<64, 256>>>(pd_scores, out);

    // join + final scatter
    cudaStreamWaitEvent(0, evK3s, 0);
    cudaStreamWaitEvent(0, evJoin, 0);
    k4_scatter<<<64, 256>>>(out);
}